// round 1
// baseline (speedup 1.0000x reference)
#include <cuda_runtime.h>
#include <cuda_bf16.h>
#include <math.h>

// ---------------- problem constants ----------------
#define BATCH 64
#define SEQ   64
#define EMB   256
#define UNITS 512
#define GRU   256
#define FC    1024
#define VOCAB 50000

// ---------------- scratch (device globals; no allocation allowed) ----------------
__device__ float g_hidproj[BATCH * UNITS];        // hidden@W2 + b2
__device__ float g_qp[BATCH * SEQ * UNITS];       // qs@W1 + b1   (4096 x 512) = 8MB
__device__ float g_score[BATCH * SEQ];            // attention logits
__device__ float g_gx[BATCH * 2 * EMB];           // [embed | context]
__device__ float g_fcin[BATCH * (GRU + UNITS)];   // [state | features] (64 x 768)
__device__ float g_t1[BATCH * FC];
__device__ float g_t2[BATCH * FC];

// ---------------- generic tiled GEMM: C[M,N] = A[M,K] @ B[K,N] + bias ----------------
// Block tile: 64 rows x 128 cols, 256 threads, 8x4 register tile per thread.
// M must be a multiple of 64, K a multiple of 32; N guarded.
__global__ __launch_bounds__(256) void gemm64x128(
    const float* __restrict__ A, const float* __restrict__ B,
    const float* __restrict__ bias, float* __restrict__ C,
    int M, int N, int K)
{
    __shared__ float  As[32][65];   // [k][m], padded to kill store conflicts
    __shared__ float4 Bs[32][32];   // [k][n4]

    const int tid = threadIdx.x;
    const int tx = tid & 31;        // column group (x4)
    const int ty = tid >> 5;        // row within group of 8
    const int n0 = blockIdx.x * 128;
    const int m0 = blockIdx.y * 64;

    float acc[8][4];
#pragma unroll
    for (int i = 0; i < 8; i++)
#pragma unroll
        for (int j = 0; j < 4; j++) acc[i][j] = 0.f;

    for (int k0 = 0; k0 < K; k0 += 32) {
        // stage A: 64x32  (coalesced along k)
#pragma unroll
        for (int e = 0; e < 8; e++) {
            int idx = tid + e * 256;      // 0..2047
            int k = idx & 31, m = idx >> 5;
            As[k][m] = A[(m0 + m) * K + (k0 + k)];
        }
        // stage B: 32x128 floats = 1024 float4 (coalesced along n)
#pragma unroll
        for (int e = 0; e < 4; e++) {
            int idx = tid + e * 256;      // 0..1023
            int k = idx >> 5, n4 = idx & 31;
            int n = n0 + n4 * 4;
            float4 v = make_float4(0.f, 0.f, 0.f, 0.f);
            if (n + 3 < N) {
                v = *(const float4*)&B[(k0 + k) * N + n];
            } else if (n < N) {
                float t0 = B[(k0 + k) * N + n];
                float t1 = (n + 1 < N) ? B[(k0 + k) * N + n + 1] : 0.f;
                float t2 = (n + 2 < N) ? B[(k0 + k) * N + n + 2] : 0.f;
                v = make_float4(t0, t1, t2, 0.f);
            }
            Bs[k][n4] = v;
        }
        __syncthreads();

#pragma unroll
        for (int kk = 0; kk < 32; kk++) {
            float4 b = Bs[kk][tx];
            float a[8];
#pragma unroll
            for (int i = 0; i < 8; i++) a[i] = As[kk][ty + 8 * i];  // warp broadcast
#pragma unroll
            for (int i = 0; i < 8; i++) {
                acc[i][0] = fmaf(a[i], b.x, acc[i][0]);
                acc[i][1] = fmaf(a[i], b.y, acc[i][1]);
                acc[i][2] = fmaf(a[i], b.z, acc[i][2]);
                acc[i][3] = fmaf(a[i], b.w, acc[i][3]);
            }
        }
        __syncthreads();
    }

    const int nbase = n0 + tx * 4;
#pragma unroll
    for (int i = 0; i < 8; i++) {
        int m = m0 + ty + 8 * i;
#pragma unroll
        for (int j = 0; j < 4; j++) {
            int n = nbase + j;
            if (n < N) C[m * N + n] = acc[i][j] + (bias ? bias[n] : 0.f);
        }
    }
}

// ---------------- hidden @ W2 + b2 : (64,512) ----------------
__global__ __launch_bounds__(512) void hidproj_k(
    const float* __restrict__ hidden, const float* __restrict__ W2,
    const float* __restrict__ b2, float* __restrict__ out)
{
    __shared__ float sh[UNITS];
    int b = blockIdx.x, t = threadIdx.x;
    sh[t] = hidden[b * UNITS + t];
    __syncthreads();
    float acc = b2[t];
#pragma unroll 8
    for (int k = 0; k < UNITS; k++) acc = fmaf(sh[k], W2[k * UNITS + t], acc);
    out[b * UNITS + t] = acc;
}

// ---------------- score[b,s] = V . tanh(qp[b,s,:] + hidproj[b,:]) + bV ----------------
__global__ __launch_bounds__(256) void score_k(
    const float* __restrict__ qp, const float* __restrict__ hidproj,
    const float* __restrict__ V, const float* __restrict__ bV,
    float* __restrict__ score)
{
    int bs = blockIdx.x;            // 0..4095
    int b = bs >> 6;
    int t = threadIdx.x;
    const float* qrow = qp + bs * UNITS;
    const float* hp = hidproj + b * UNITS;
    float s = 0.f;
    for (int u = t; u < UNITS; u += 256)
        s += tanhf(qrow[u] + hp[u]) * V[u];
    __shared__ float red[256];
    red[t] = s; __syncthreads();
    for (int o = 128; o > 0; o >>= 1) {
        if (t < o) red[t] += red[t + o];
        __syncthreads();
    }
    if (t == 0) score[bs] = red[0] + bV[0];
}

// ---------------- softmax over S, context, embedding gather -> gx ----------------
__global__ __launch_bounds__(256) void softctx_k(
    const float* __restrict__ score, const float* __restrict__ qs,
    const int* __restrict__ x, const float* __restrict__ E,
    float* __restrict__ weights_out, float* __restrict__ gx)
{
    int b = blockIdx.x, t = threadIdx.x;
    __shared__ float w[SEQ];
    if (t < SEQ) w[t] = score[b * SEQ + t];
    __syncthreads();
    if (t == 0) {
        float mx = w[0];
        for (int s = 1; s < SEQ; s++) mx = fmaxf(mx, w[s]);
        float sum = 0.f;
        for (int s = 0; s < SEQ; s++) { w[s] = expf(w[s] - mx); sum += w[s]; }
        float inv = 1.f / sum;
        for (int s = 0; s < SEQ; s++) w[s] *= inv;
    }
    __syncthreads();
    if (t < SEQ) weights_out[b * SEQ + t] = w[t];
    // context over e = t (0..255)
    float c = 0.f;
#pragma unroll 8
    for (int s = 0; s < SEQ; s++)
        c = fmaf(w[s], qs[(b * SEQ + s) * EMB + t], c);
    gx[b * 2 * EMB + EMB + t] = c;
    gx[b * 2 * EMB + t] = E[x[b] * EMB + t];
}

// ---------------- GRU step with h0 = 0 ----------------
__global__ __launch_bounds__(256) void gru_k(
    const float* __restrict__ gx, const float* __restrict__ Kg,
    const float* __restrict__ bg, const float* __restrict__ features,
    float* __restrict__ state_out, float* __restrict__ fc_in)
{
    int b = blockIdx.x, g = threadIdx.x;   // g in 0..255
    __shared__ float sh[2 * EMB];
    sh[g] = gx[b * 2 * EMB + g];
    sh[g + 256] = gx[b * 2 * EMB + 256 + g];
    __syncthreads();
    float mz = bg[g], mr = bg[GRU + g], mh = bg[2 * GRU + g];
#pragma unroll 4
    for (int k = 0; k < 2 * EMB; k++) {
        float a = sh[k];
        const float* kr = Kg + k * 3 * GRU;
        mz = fmaf(a, kr[g], mz);
        mr = fmaf(a, kr[GRU + g], mr);
        mh = fmaf(a, kr[2 * GRU + g], mh);
    }
    const float* bgh = bg + 3 * GRU;       // bg[1]
    float z = 1.f / (1.f + expf(-(mz + bgh[g])));
    float r = 1.f / (1.f + expf(-(mr + bgh[GRU + g])));
    float hc = tanhf(mh + r * bgh[2 * GRU + g]);
    float st = (1.f - z) * hc;             // z*h0 term is zero
    state_out[b * GRU + g] = st;
    fc_in[b * (GRU + UNITS) + g] = st;
    fc_in[b * (GRU + UNITS) + GRU + g] = features[b * UNITS + g];
    fc_in[b * (GRU + UNITS) + GRU + 256 + g] = features[b * UNITS + 256 + g];
}

// ---------------- naive dense: out[b,o] = in[b,:] . W[:,o] + bias[o] ----------------
__global__ void dense_k(const float* __restrict__ in, const float* __restrict__ W,
                        const float* __restrict__ bias, float* __restrict__ out,
                        int IN, int OUT)
{
    extern __shared__ float sh[];
    int b = blockIdx.y;
    int o = blockIdx.x * blockDim.x + threadIdx.x;
    for (int k = threadIdx.x; k < IN; k += blockDim.x) sh[k] = in[b * IN + k];
    __syncthreads();
    float acc = bias[o];
#pragma unroll 8
    for (int k = 0; k < IN; k++) acc = fmaf(sh[k], W[k * OUT + o], acc);
    out[b * OUT + o] = acc;
}

// ---------------- launch ----------------
extern "C" void kernel_launch(void* const* d_in, const int* in_sizes, int n_in,
                              void* d_out, int out_size)
{
    const int*   x        = (const int*)  d_in[0];
    const float* qs       = (const float*)d_in[1];
    const float* features = (const float*)d_in[2];
    const float* hidden   = (const float*)d_in[3];
    const float* E        = (const float*)d_in[4];
    const float* W1       = (const float*)d_in[5];
    const float* b1       = (const float*)d_in[6];
    const float* W2       = (const float*)d_in[7];
    const float* b2       = (const float*)d_in[8];
    const float* V        = (const float*)d_in[9];
    const float* bV       = (const float*)d_in[10];
    const float* Kg       = (const float*)d_in[11];
    /* d_in[12] = Ug is dead: h0 == 0 */
    const float* bg       = (const float*)d_in[13];
    const float* Wf1      = (const float*)d_in[14];
    const float* bf1      = (const float*)d_in[15];
    const float* Wf2      = (const float*)d_in[16];
    const float* bf2      = (const float*)d_in[17];
    const float* Wo       = (const float*)d_in[18];
    const float* bo       = (const float*)d_in[19];

    float* out = (float*)d_out;
    float* logits      = out;                               // 64*50000
    float* state_out   = out + BATCH * VOCAB;               // 64*256
    float* weights_out = state_out + BATCH * GRU;           // 64*64

    float *qp, *hidproj, *score, *gx, *fcin, *t1, *t2;
    cudaGetSymbolAddress((void**)&qp,      g_qp);
    cudaGetSymbolAddress((void**)&hidproj, g_hidproj);
    cudaGetSymbolAddress((void**)&score,   g_score);
    cudaGetSymbolAddress((void**)&gx,      g_gx);
    cudaGetSymbolAddress((void**)&fcin,    g_fcin);
    cudaGetSymbolAddress((void**)&t1,      g_t1);
    cudaGetSymbolAddress((void**)&t2,      g_t2);

    // attention projections
    hidproj_k<<<BATCH, UNITS>>>(hidden, W2, b2, hidproj);
    gemm64x128<<<dim3(UNITS / 128, (BATCH * SEQ) / 64), 256>>>(
        qs, W1, b1, qp, BATCH * SEQ, UNITS, EMB);
    score_k<<<BATCH * SEQ, 256>>>(qp, hidproj, V, bV, score);
    softctx_k<<<BATCH, 256>>>(score, qs, x, E, weights_out, gx);
    // GRU (h0 = 0)
    gru_k<<<BATCH, 256>>>(gx, Kg, bg, features, state_out, fcin);
    // dense stack
    dense_k<<<dim3(FC / 256, BATCH), 256, (GRU + UNITS) * sizeof(float)>>>(
        fcin, Wf1, bf1, t1, GRU + UNITS, FC);
    dense_k<<<dim3(FC / 256, BATCH), 256, FC * sizeof(float)>>>(
        t1, Wf2, bf2, t2, FC, FC);
    // logits: 64 x 50000, K = 1024 (dominant cost)
    gemm64x128<<<dim3((VOCAB + 127) / 128, 1), 256>>>(
        t2, Wo, bo, logits, BATCH, VOCAB, FC);
}